// round 3
// baseline (speedup 1.0000x reference)
#include <cuda_runtime.h>

// Problem constants
#define NROWS   524288
#define DIN     64
#define DOUT    128
#define TN      64                    // rows per tile
#define NTHREADS 256
#define NBLOCKS 296                   // 2 per SM on 148 SMs
#define NTILES  (NROWS / TN)          // 8192
#define XS      68                    // padded smem row stride (floats) for x tile
#define CS      68                    // padded smem row stride for centers
#define THRESH  1e-16f                // rbf significance cutoff for GEMM2 row skip

#define SMEM_FLOATS (TN*XS + DOUT*CS + TN*DOUT + TN + DOUT + TN)
#define SMEM_BYTES  (SMEM_FLOATS * 4)   // 86016 B

// Per-block partial histograms (deterministic reduction, no atomics)
__device__ float g_partial[NBLOCKS][DOUT * DIN];

__global__ void __launch_bounds__(NTHREADS, 2)
hist_main_kernel(const float* __restrict__ gx, const float* __restrict__ gc)
{
    extern __shared__ float smem[];
    float* x_s   = smem;                       // TN * XS
    float* c_s   = smem + TN * XS;             // DOUT * CS
    float* rbf_s = c_s + DOUT * CS;            // TN * DOUT
    float* x2_s  = rbf_s + TN * DOUT;          // TN
    float* c2_s  = x2_s + TN;                  // DOUT
    int*   flags = (int*)(c2_s + DOUT);        // TN

    const int tid = threadIdx.x;
    const int bid = blockIdx.x;
    const int og  = tid >> 3;   // 0..31  -> o block of 4 (phase A and B)
    const int ig  = tid & 7;    // 0..7   -> i block of 8 (phase B)
    const int rg  = tid & 7;    // 0..7   -> row lane (phase A)

    // ---- Load centers once (row-major [128][64] -> padded smem) ----
    #pragma unroll
    for (int l = 0; l < (DOUT * DIN / 4) / NTHREADS; l++) {   // 8 iters
        int idx = tid + l * NTHREADS;
        float4 v = ((const float4*)gc)[idx];
        int r   = idx >> 4;           // 16 float4 per row
        int col = (idx & 15) * 4;
        *(float4*)(c_s + r * CS + col) = v;
    }
    __syncthreads();
    if (tid < DOUT) {
        float s = 0.f;
        const float* cr = c_s + tid * CS;
        #pragma unroll
        for (int k = 0; k < DIN; k++) s = fmaf(cr[k], cr[k], s);
        c2_s[tid] = s;
    }
    // (c2_s consumed only after the syncthreads inside the tile loop)

    // Persistent histogram accumulators: thread owns o = og*4+jo, i = ig*8+ji
    float accH[4][8];
    #pragma unroll
    for (int a = 0; a < 4; a++)
        #pragma unroll
        for (int b = 0; b < 8; b++) accH[a][b] = 0.f;

    for (int tile = bid; tile < NTILES; tile += NBLOCKS) {
        __syncthreads();   // previous tile's phase B must finish before x_s/flags reuse

        // ---- Stage x tile ----
        const float* xt = gx + (size_t)tile * (TN * DIN);
        #pragma unroll
        for (int l = 0; l < (TN * DIN / 4) / NTHREADS; l++) { // 4 iters
            int idx = tid + l * NTHREADS;
            float4 v = ((const float4*)xt)[idx];
            int r   = idx >> 4;
            int col = (idx & 15) * 4;
            *(float4*)(x_s + r * XS + col) = v;
        }
        if (tid < TN) flags[tid] = 0;
        __syncthreads();
        if (tid < TN) {
            float s = 0.f;
            const float* xr = x_s + tid * XS;
            #pragma unroll
            for (int k = 0; k < DIN; k++) s = fmaf(xr[k], xr[k], s);
            x2_s[tid] = s;
        }
        __syncthreads();

        // ---- Phase A: rbf[r][o] for r = rg + 8*m (m=0..7), o = og*4 + jo ----
        {
            const float* cb = c_s + (og * 4) * CS;
            float c2v[4];
            #pragma unroll
            for (int jo = 0; jo < 4; jo++) c2v[jo] = c2_s[og * 4 + jo];

            #pragma unroll
            for (int half = 0; half < 2; half++) {
                float acc[4][4];
                #pragma unroll
                for (int a = 0; a < 4; a++)
                    #pragma unroll
                    for (int b = 0; b < 4; b++) acc[a][b] = 0.f;

                const float* xb = x_s + rg * XS;   // + 8*(half*4+jr)*XS per row
                #pragma unroll
                for (int k = 0; k < DIN; k += 4) {
                    float4 ca[4];
                    #pragma unroll
                    for (int jo = 0; jo < 4; jo++)
                        ca[jo] = *(const float4*)(cb + jo * CS + k);
                    #pragma unroll
                    for (int jr = 0; jr < 4; jr++) {
                        float4 xa = *(const float4*)(xb + (half * 4 + jr) * 8 * XS + k);
                        #pragma unroll
                        for (int jo = 0; jo < 4; jo++) {
                            acc[jr][jo] = fmaf(xa.x, ca[jo].x, acc[jr][jo]);
                            acc[jr][jo] = fmaf(xa.y, ca[jo].y, acc[jr][jo]);
                            acc[jr][jo] = fmaf(xa.z, ca[jo].z, acc[jr][jo]);
                            acc[jr][jo] = fmaf(xa.w, ca[jo].w, acc[jr][jo]);
                        }
                    }
                }

                #pragma unroll
                for (int jr = 0; jr < 4; jr++) {
                    int r = rg + 8 * (half * 4 + jr);
                    float x2v = x2_s[r];
                    float4 rb4;
                    float* rbp = (float*)&rb4;
                    int f = 0;
                    #pragma unroll
                    for (int jo = 0; jo < 4; jo++) {
                        float dist = (x2v + c2v[jo]) - 2.f * acc[jr][jo];
                        float rb = __expf(-0.5f * dist);
                        rbp[jo] = rb;
                        if (rb > THRESH) f = 1;
                    }
                    *(float4*)(rbf_s + r * DOUT + og * 4) = rb4;
                    if (f) flags[r] = 1;   // benign race: everyone writes 1
                }
            }
        }
        __syncthreads();

        // ---- Phase B: accH[o][i] += sum_n rbf[n][o] * x[n][i], skipping dead rows ----
        {
            #pragma unroll 2
            for (int n = 0; n < TN; n++) {
                if (flags[n] == 0) continue;    // uniform across block
                float4 rb = *(const float4*)(rbf_s + n * DOUT + og * 4);
                const float* xr = x_s + n * XS + ig * 8;
                float4 xv0 = *(const float4*)(xr);
                float4 xv1 = *(const float4*)(xr + 4);
                #pragma unroll
                for (int jo = 0; jo < 4; jo++) {
                    float rv = ((float*)&rb)[jo];
                    accH[jo][0] = fmaf(rv, xv0.x, accH[jo][0]);
                    accH[jo][1] = fmaf(rv, xv0.y, accH[jo][1]);
                    accH[jo][2] = fmaf(rv, xv0.z, accH[jo][2]);
                    accH[jo][3] = fmaf(rv, xv0.w, accH[jo][3]);
                    accH[jo][4] = fmaf(rv, xv1.x, accH[jo][4]);
                    accH[jo][5] = fmaf(rv, xv1.y, accH[jo][5]);
                    accH[jo][6] = fmaf(rv, xv1.z, accH[jo][6]);
                    accH[jo][7] = fmaf(rv, xv1.w, accH[jo][7]);
                }
            }
        }
    }

    // ---- Write this block's partial histogram ----
    float* dst = &g_partial[bid][0];
    #pragma unroll
    for (int jo = 0; jo < 4; jo++) {
        int o = og * 4 + jo;
        *(float4*)(dst + o * DIN + ig * 8)     =
            make_float4(accH[jo][0], accH[jo][1], accH[jo][2], accH[jo][3]);
        *(float4*)(dst + o * DIN + ig * 8 + 4) =
            make_float4(accH[jo][4], accH[jo][5], accH[jo][6], accH[jo][7]);
    }
}

__global__ void hist_reduce_kernel(float* __restrict__ out)
{
    int e = blockIdx.x * blockDim.x + threadIdx.x;  // 0..8191
    float s = 0.f;
    #pragma unroll 8
    for (int b = 0; b < NBLOCKS; b++) s += g_partial[b][e];
    out[e] = s;
}

extern "C" void kernel_launch(void* const* d_in, const int* in_sizes, int n_in,
                              void* d_out, int out_size)
{
    const float* x = (const float*)d_in[0];
    const float* c = (const float*)d_in[1];
    // Robustness: identify which input is which by size
    if (n_in >= 2 && in_sizes[0] == DOUT * DIN && in_sizes[1] == NROWS * DIN) {
        x = (const float*)d_in[1];
        c = (const float*)d_in[0];
    }

    cudaFuncSetAttribute(hist_main_kernel,
                         cudaFuncAttributeMaxDynamicSharedMemorySize, SMEM_BYTES);

    hist_main_kernel<<<NBLOCKS, NTHREADS, SMEM_BYTES>>>(x, c);
    hist_reduce_kernel<<<(DOUT * DIN) / 256, 256>>>((float*)d_out);
}